// round 5
// baseline (speedup 1.0000x reference)
#include <cuda_runtime.h>
#include <math.h>

#define NN 2000
#define KK 20
#define BB 16
#define CC 32
#define TT 13
#define DD 416        // C*T
#define ALPHA 0.05f
#define NSLOPE 0.2f
#define OMA (1.0f - ALPHA)

// fused propagation chunking
#define DC 8                   // floats per d-chunk
#define NCH (DD/DC)            // 52 chunks
#define SSTR 12                // smem row stride in floats (48B, 16B-aligned)
#define SLICE (NN*SSTR)        // floats per slice buffer (24000)
#define PROP_SMEM (2*SLICE*4)  // 192000 B: x-slice + h1-slice
// swizzled row offset: rotation by 4 floats keyed off bit3 decorrelates quad-slot
// assignment while keeping float4 alignment and the row inside its 12-float slot
#define ROFF(n) ((n)*SSTR + (((n)>>3)&1)*4)

// ---------------- scratch (device globals; no allocation allowed) ----------------
__device__ float g_adjw[NN*KK];
__device__ int   g_idx[NN*KK];
__device__ float g_u1[DD];
__device__ float g_u2[DD];
__device__ float g_cst[2];
__device__ float g_left[BB*NN];
__device__ float g_right[BB*NN];
__device__ float g_Rs[BB*2048];
__device__ float g_suf[BB*2048];   // suf[i] = sum_{j>=i} exp(Rs[j])
__device__ float g_pre[BB*2048];   // pre[i] = sum_{j< i} exp(0.2*Rs[j])
__device__ __align__(16) float g_wi[(size_t)BB*NN*KK*2]; // packed (w, idx-as-float)
__device__ float g_h2[(size_t)BB*DD*NN];  // h after GDEP iters, layout [b][d][n]

// ---------------- 1) adj: relu, row-sum, top-K, normalized weights ----------------
__global__ void k_topk(const float* __restrict__ adj){
  int m = blockIdx.x;
  __shared__ float sv[NN];
  __shared__ float rv[256];
  __shared__ int   ri[256];
  __shared__ float s_deg;
  int tid = threadIdx.x;
  float s = 0.f;
  for (int n = tid; n < NN; n += 256){
    float v = adj[(size_t)m*NN + n];
    v = v > 0.f ? v : 0.f;
    sv[n] = v; s += v;
  }
  rv[tid] = s; __syncthreads();
  for (int st = 128; st > 0; st >>= 1){ if (tid < st) rv[tid] += rv[tid+st]; __syncthreads(); }
  if (tid == 0) s_deg = rv[0];
  __syncthreads();
  float inv_deg = 1.f / s_deg;
  for (int k = 0; k < KK; k++){
    float best = -1.f; int bi = NN;
    for (int n = tid; n < NN; n += 256){
      float v = sv[n];
      if (v > best){ best = v; bi = n; }   // strict > keeps lowest index on ties
    }
    rv[tid] = best; ri[tid] = bi; __syncthreads();
    for (int st = 128; st > 0; st >>= 1){
      if (tid < st){
        float v2 = rv[tid+st]; int i2 = ri[tid+st];
        if (v2 > rv[tid] || (v2 == rv[tid] && i2 < ri[tid])){ rv[tid] = v2; ri[tid] = i2; }
      }
      __syncthreads();
    }
    if (tid == 0){
      int bx = ri[0];
      g_idx[m*KK+k]  = bx;
      g_adjw[m*KK+k] = rv[0] * inv_deg;
      sv[bx] = -2.f;
    }
    __syncthreads();
  }
}

// ---------------- 2) fold W2,b2,a into u1,u2,consts ----------------
__global__ void k_prep(const float* __restrict__ W2, const float* __restrict__ b2,
                       const float* __restrict__ a){
  int d = blockIdx.x*blockDim.x + threadIdx.x;
  if (d < DD){
    int c = d / TT, t = d - c*TT;
    float s1 = 0.f, s2 = 0.f;
    for (int co = 0; co < CC; co++){
      float w = W2[co*CC + c];
      s1 += w * a[t*CC + co];
      s2 += w * a[DD + t*CC + co];
    }
    g_u1[d] = s1; g_u2[d] = s2;
  }
  if (blockIdx.x == 0 && threadIdx.x == 0){
    float c1 = 0.f, c2 = 0.f;
    for (int t = 0; t < TT; t++)
      for (int co = 0; co < CC; co++){
        c1 += b2[co]*a[t*CC+co];
        c2 += b2[co]*a[DD + t*CC+co];
      }
    g_cst[0] = c1; g_cst[1] = c2;
  }
}

// ---------------- 3) left/right = x . u1/u2 (coalesced over n) ----------------
__global__ void k_lr(const float* __restrict__ x){
  int b = blockIdx.y;
  int n = blockIdx.x*256 + threadIdx.x;
  __shared__ float su1[DD], su2[DD];
  for (int d = threadIdx.x; d < DD; d += 256){ su1[d] = g_u1[d]; su2[d] = g_u2[d]; }
  __syncthreads();
  if (n >= NN) return;
  const float* xp = x + (size_t)b*DD*NN + n;
  float l = g_cst[0], r = g_cst[1];
  #pragma unroll 4
  for (int d = 0; d < DD; d++){
    float v = __ldg(xp + (size_t)d*NN);
    l += v*su1[d]; r += v*su2[d];
  }
  g_left[b*NN+n] = l; g_right[b*NN+n] = r;
}

// ---------------- 4) per-batch: sort R, suffix/prefix exp-sums (double scan) ----------------
__global__ void k_sortscan(){
  int b = blockIdx.x;
  int t = threadIdx.x;  // 1024
  __shared__ float  s[2048];
  __shared__ double part[1024];
  __shared__ double s_tot;
  for (int i = t; i < 2048; i += 1024) s[i] = (i < NN) ? g_right[b*NN+i] : 3.0e38f;
  __syncthreads();
  // bitonic ascending sort of 2048
  for (int ksz = 2; ksz <= 2048; ksz <<= 1){
    for (int j = ksz >> 1; j > 0; j >>= 1){
      for (int idx = t; idx < 2048; idx += 1024){
        int p = idx ^ j;
        if (p > idx){
          float a0 = s[idx], a1 = s[p];
          bool up = ((idx & ksz) == 0);
          if ((a0 > a1) == up){ s[idx] = a1; s[p] = a0; }
        }
      }
      __syncthreads();
    }
  }
  for (int i = t; i < NN; i += 1024) g_Rs[b*2048+i] = s[i];
  __syncthreads();

  // pass 1: prefix of exp(Rs) -> suffix sums
  float v0 = (2*t   < NN) ? expf(s[2*t])   : 0.f;
  float v1 = (2*t+1 < NN) ? expf(s[2*t+1]) : 0.f;
  double lsum = (double)v0 + (double)v1;
  part[t] = lsum; __syncthreads();
  for (int off = 1; off < 1024; off <<= 1){
    double tv = (t >= off) ? part[t-off] : 0.0;
    __syncthreads();
    part[t] += tv;
    __syncthreads();
  }
  if (t == 1023) s_tot = part[1023];
  __syncthreads();
  {
    double excl = part[t] - lsum;
    double tot  = s_tot;
    g_suf[b*2048 + 2*t]   = (float)(tot - excl);
    g_suf[b*2048 + 2*t+1] = (float)(tot - (excl + (double)v0));
  }
  __syncthreads();

  // pass 2: prefix of exp(0.2*Rs)
  v0 = (2*t   < NN) ? expf(0.2f*s[2*t])   : 0.f;
  v1 = (2*t+1 < NN) ? expf(0.2f*s[2*t+1]) : 0.f;
  lsum = (double)v0 + (double)v1;
  part[t] = lsum; __syncthreads();
  for (int off = 1; off < 1024; off <<= 1){
    double tv = (t >= off) ? part[t-off] : 0.0;
    __syncthreads();
    part[t] += tv;
    __syncthreads();
  }
  {
    double excl = part[t] - lsum;
    g_pre[b*2048 + 2*t]   = (float)excl;
    g_pre[b*2048 + 2*t+1] = (float)(excl + (double)v0);
  }
}

// ---------------- 5) edge weights: packed (attention+adj1, idx) at top-K ----------------
__global__ void k_weights(){
  int g = blockIdx.x*256 + threadIdx.x;
  if (g >= BB*NN) return;
  int b = g / NN;
  int m = g - b*NN;
  float L = g_left[g];
  float negL = -L;
  const float* Rs = g_Rs + b*2048;
  int lo = 0, hi = NN;
  while (lo < hi){ int mid = (lo+hi) >> 1; if (Rs[mid] < negL) lo = mid+1; else hi = mid; }
  // denom = sum_n exp(lrelu(L+R_n)) ; split at R = -L
  float denom = expf(L)*g_suf[b*2048+lo] + expf(0.2f*L)*g_pre[b*2048+lo];
  float inv = 1.f/denom;
  float* wo = g_wi + (size_t)g*KK*2;
  #pragma unroll
  for (int k = 0; k < KK; k++){
    int n = g_idx[m*KK+k];
    float R = g_right[b*NN+n];
    float z = L + R;
    float e = (z >= 0.f) ? z : NSLOPE*z;
    wo[2*k]   = expf(e)*inv + g_adjw[m*KK+k];
    wo[2*k+1] = __int_as_float(n);
  }
}

// ---------------- 6) fused 2-iteration propagation, per (b, d-chunk) ----------------
// block = (chunk, b). Stage x[b][d0:d0+8][:] into swizzled smem slice,
// run BOTH GDEP iterations in smem, write h2 directly in [b][d][n] layout.
// TWO lanes per row m: each lane reads one float4 half -> quarter-warp issues
// 4 adjacent-slot "dominoes" (max-load ~2.0) instead of 8 free slots (~2.3).
__global__ __launch_bounds__(1024, 1) void k_propf(const float* __restrict__ x){
  extern __shared__ float sm[];
  float* sx = sm;          // x slice
  float* sh = sm + SLICE;  // h1 slice
  int b  = blockIdx.y;
  int d0 = blockIdx.x * DC;
  int tid = threadIdx.x;
  // stage: coalesced reads of 8 contiguous rows of x
  #pragma unroll
  for (int dl = 0; dl < DC; dl++){
    const float* xr = x + ((size_t)b*DD + d0 + dl)*NN;
    for (int n = tid; n < NN; n += 1024) sx[ROFF(n) + dl] = __ldg(xr + n);
  }
  __syncthreads();

  int mlane = tid >> 1;        // 512 m-lanes
  int h4    = (tid & 1) * 4;   // which float4 half of the 8-float chunk

  // iter 1: h1 = a*x + (1-a) * sum_k w_k x[idx_k]   (into sh)
  #pragma unroll
  for (int j = 0; j < 4; j++){
    int m = j*512 + mlane;
    if (m < NN){
      const float4* wi = reinterpret_cast<const float4*>(g_wi + ((size_t)(b*NN+m))*(KK*2));
      float ax=0.f, ay=0.f, az=0.f, aw=0.f;
      #pragma unroll
      for (int kk = 0; kk < KK/2; kk++){
        float4 p = __ldg(wi + kk);
        const float4 v1 = *reinterpret_cast<const float4*>(sx + ROFF(__float_as_int(p.y)) + h4);
        ax += p.x*v1.x; ay += p.x*v1.y; az += p.x*v1.z; aw += p.x*v1.w;
        const float4 v2 = *reinterpret_cast<const float4*>(sx + ROFF(__float_as_int(p.w)) + h4);
        ax += p.z*v2.x; ay += p.z*v2.y; az += p.z*v2.z; aw += p.z*v2.w;
      }
      int rm = ROFF(m) + h4;
      float4 xm = *reinterpret_cast<const float4*>(sx + rm);
      float4 r;
      r.x = ALPHA*xm.x + OMA*ax;
      r.y = ALPHA*xm.y + OMA*ay;
      r.z = ALPHA*xm.z + OMA*az;
      r.w = ALPHA*xm.w + OMA*aw;
      *reinterpret_cast<float4*>(sh + rm) = r;    // sh unread until sync
    }
  }
  __syncthreads();

  // iter 2: h2 = a*x + (1-a) * sum_k w_k h1[idx_k]   (to global, [b][d][n])
  #pragma unroll
  for (int j = 0; j < 4; j++){
    int m = j*512 + mlane;
    if (m < NN){
      const float4* wi = reinterpret_cast<const float4*>(g_wi + ((size_t)(b*NN+m))*(KK*2));
      float ax=0.f, ay=0.f, az=0.f, aw=0.f;
      #pragma unroll
      for (int kk = 0; kk < KK/2; kk++){
        float4 p = __ldg(wi + kk);
        const float4 v1 = *reinterpret_cast<const float4*>(sh + ROFF(__float_as_int(p.y)) + h4);
        ax += p.x*v1.x; ay += p.x*v1.y; az += p.x*v1.z; aw += p.x*v1.w;
        const float4 v2 = *reinterpret_cast<const float4*>(sh + ROFF(__float_as_int(p.w)) + h4);
        ax += p.z*v2.x; ay += p.z*v2.y; az += p.z*v2.z; aw += p.z*v2.w;
      }
      float4 xm = *reinterpret_cast<const float4*>(sx + ROFF(m) + h4);
      float r0 = ALPHA*xm.x + OMA*ax;
      float r1 = ALPHA*xm.y + OMA*ay;
      float r2 = ALPHA*xm.z + OMA*az;
      float r3 = ALPHA*xm.w + OMA*aw;
      size_t o = ((size_t)b*DD + d0 + h4)*NN + m;  // [b][d][n]
      g_h2[o]        = r0;
      g_h2[o + NN]   = r1;
      g_h2[o + 2*NN] = r2;
      g_h2[o + 3*NN] = r3;
    }
  }
}

// ---------------- 7) output: ho[b,o,t,n] = W1 @ h2 + b1 (h2 in [b][d][n]) ----------------
__global__ void k_out(const float* __restrict__ W1, const float* __restrict__ b1,
                      float* __restrict__ out){
  __shared__ __align__(16) float w1s[32*36];  // [o][c] padded
  __shared__ float b1s[32];
  int b = blockIdx.z;
  int t = blockIdx.y;
  int n = blockIdx.x*256 + threadIdx.x;
  for (int i = threadIdx.x; i < 1024; i += 256){ int o = i >> 5, c = i & 31; w1s[o*36 + c] = W1[i]; }
  if (threadIdx.x < 32) b1s[threadIdx.x] = b1[threadIdx.x];
  __syncthreads();
  if (n >= NN) return;
  float xv[CC];
  const float* hp = g_h2 + ((size_t)b*DD + t)*NN + n;
  #pragma unroll
  for (int c = 0; c < CC; c++) xv[c] = __ldg(hp + (size_t)c*TT*NN);
  size_t ob = ((size_t)b*CC*TT + t)*NN + n;
  #pragma unroll
  for (int o = 0; o < CC; o++){
    float acc = b1s[o];
    const float4* wr = reinterpret_cast<const float4*>(w1s + o*36);
    #pragma unroll
    for (int c4 = 0; c4 < CC/4; c4++){
      float4 w = wr[c4];
      acc += w.x*xv[4*c4] + w.y*xv[4*c4+1] + w.z*xv[4*c4+2] + w.w*xv[4*c4+3];
    }
    out[ob + (size_t)o*TT*NN] = acc;
  }
}

// ---------------- launch ----------------
extern "C" void kernel_launch(void* const* d_in, const int* in_sizes, int n_in,
                              void* d_out, int out_size){
  const float* x   = (const float*)d_in[0];
  const float* adj = (const float*)d_in[1];
  const float* W1  = (const float*)d_in[2];
  const float* b1  = (const float*)d_in[3];
  const float* W2  = (const float*)d_in[4];
  const float* b2  = (const float*)d_in[5];
  const float* a   = (const float*)d_in[6];
  float* out = (float*)d_out;

  cudaFuncSetAttribute(k_propf, cudaFuncAttributeMaxDynamicSharedMemorySize, PROP_SMEM);

  k_topk<<<NN, 256>>>(adj);
  k_prep<<<2, 256>>>(W2, b2, a);
  k_lr<<<dim3((NN+255)/256, BB), 256>>>(x);
  k_sortscan<<<BB, 1024>>>();
  k_weights<<<(BB*NN+255)/256, 256>>>();
  k_propf<<<dim3(NCH, BB), 1024, PROP_SMEM>>>(x);
  k_out<<<dim3((NN+255)/256, TT, BB), 256>>>(W1, b1, out);
}

// round 6
// speedup vs baseline: 1.1749x; 1.1749x over previous
#include <cuda_runtime.h>
#include <math.h>

#define NN 2000
#define KK 20
#define BB 16
#define CC 32
#define TT 13
#define DD 416        // C*T
#define ALPHA 0.05f
#define NSLOPE 0.2f
#define OMA (1.0f - ALPHA)

// fused propagation chunking
#define DC 8                   // floats per d-chunk
#define NCH (DD/DC)            // 52 chunks
#define SSTR 12                // smem row stride in floats (48B, 16B-aligned)
#define SLICE (NN*SSTR)        // floats per slice buffer (24000)
#define PROP_SMEM (2*SLICE*4)  // 192000 B: x-slice + h1-slice
#define ROFF(n) ((n)*SSTR + (((n)>>3)&1)*4)

// ---------------- scratch (device globals; no allocation allowed) ----------------
__device__ float g_adjw[NN*KK];
__device__ int   g_idx[NN*KK];
__device__ float g_left[BB*NN];
__device__ float g_right[BB*NN];
__device__ float g_Rs[BB*2048];
__device__ float g_suf[BB*2048];   // suf[i] = sum_{j>=i} exp(Rs[j])
__device__ float g_pre[BB*2048];   // pre[i] = sum_{j< i} exp(0.2*Rs[j])
__device__ __align__(16) float g_wi[(size_t)BB*NN*KK*2]; // packed (w, idx-as-float)
__device__ float g_h2[(size_t)BB*DD*NN];  // h after GDEP iters, layout [b][d][n]

// ---------------- 1) FUSED front: topk (blocks 0..1999) + prep/lr (blocks 2000..2127) ----------------
__global__ void k_front(const float* __restrict__ adj, const float* __restrict__ x,
                        const float* __restrict__ W2, const float* __restrict__ b2,
                        const float* __restrict__ a){
  __shared__ union {
    struct { float sv[NN]; float rv[256]; int ri[256]; float deg; } tk;
    struct { float su1[DD]; float su2[DD]; float w2[CC*CC]; float av[2*DD]; float c1, c2; } lr;
  } u;
  int tid = threadIdx.x;

  if (blockIdx.x < NN){
    // ---- top-K for row m ----
    int m = blockIdx.x;
    float s = 0.f;
    for (int n = tid; n < NN; n += 256){
      float v = adj[(size_t)m*NN + n];
      v = v > 0.f ? v : 0.f;
      u.tk.sv[n] = v; s += v;
    }
    u.tk.rv[tid] = s; __syncthreads();
    for (int st = 128; st > 0; st >>= 1){ if (tid < st) u.tk.rv[tid] += u.tk.rv[tid+st]; __syncthreads(); }
    if (tid == 0) u.tk.deg = u.tk.rv[0];
    __syncthreads();
    float inv_deg = 1.f / u.tk.deg;
    for (int k = 0; k < KK; k++){
      float best = -1.f; int bi = NN;
      for (int n = tid; n < NN; n += 256){
        float v = u.tk.sv[n];
        if (v > best){ best = v; bi = n; }   // strict > keeps lowest index on ties
      }
      u.tk.rv[tid] = best; u.tk.ri[tid] = bi; __syncthreads();
      for (int st = 128; st > 0; st >>= 1){
        if (tid < st){
          float v2 = u.tk.rv[tid+st]; int i2 = u.tk.ri[tid+st];
          if (v2 > u.tk.rv[tid] || (v2 == u.tk.rv[tid] && i2 < u.tk.ri[tid])){
            u.tk.rv[tid] = v2; u.tk.ri[tid] = i2;
          }
        }
        __syncthreads();
      }
      if (tid == 0){
        int bx = u.tk.ri[0];
        g_idx[m*KK+k]  = bx;
        g_adjw[m*KK+k] = u.tk.rv[0] * inv_deg;
        u.tk.sv[bx] = -2.f;
      }
      __syncthreads();
    }
  } else {
    // ---- left/right for one (b, n-block), with u1/u2 folded locally ----
    int vb = blockIdx.x - NN;       // 0..127
    int b  = vb >> 3;
    int nb = vb & 7;
    for (int i = tid; i < CC*CC; i += 256) u.lr.w2[i] = W2[i];
    for (int i = tid; i < 2*DD;  i += 256) u.lr.av[i] = a[i];
    __syncthreads();
    for (int d = tid; d < DD; d += 256){
      int c = d / TT, tt = d - c*TT;
      float s1 = 0.f, s2 = 0.f;
      #pragma unroll
      for (int co = 0; co < CC; co++){
        float w = u.lr.w2[co*CC + c];
        s1 += w * u.lr.av[tt*CC + co];
        s2 += w * u.lr.av[DD + tt*CC + co];
      }
      u.lr.su1[d] = s1; u.lr.su2[d] = s2;
    }
    if (tid < 32){
      float sa1 = 0.f, sa2 = 0.f;
      #pragma unroll
      for (int tt = 0; tt < TT; tt++){
        sa1 += u.lr.av[tt*CC + tid];
        sa2 += u.lr.av[DD + tt*CC + tid];
      }
      float bb = __ldg(b2 + tid);
      float p1 = bb*sa1, p2 = bb*sa2;
      #pragma unroll
      for (int off = 16; off; off >>= 1){
        p1 += __shfl_down_sync(0xFFFFFFFFu, p1, off);
        p2 += __shfl_down_sync(0xFFFFFFFFu, p2, off);
      }
      if (tid == 0){ u.lr.c1 = p1; u.lr.c2 = p2; }
    }
    __syncthreads();
    int n = nb*256 + tid;
    if (n >= NN) return;
    const float* xp = x + (size_t)b*DD*NN + n;
    float l = u.lr.c1, r = u.lr.c2;
    for (int d0 = 0; d0 < DD; d0 += 16){     // 26 exact groups; MLP=16
      float vb16[16];
      #pragma unroll
      for (int q = 0; q < 16; q++) vb16[q] = __ldg(xp + (size_t)(d0+q)*NN);
      #pragma unroll
      for (int q = 0; q < 16; q++){
        l += vb16[q]*u.lr.su1[d0+q];
        r += vb16[q]*u.lr.su2[d0+q];
      }
    }
    g_left[b*NN+n] = l; g_right[b*NN+n] = r;
  }
}

// ---------------- 2) per-batch: bitonic sort (shfl tail) + warp-scan exp-sums ----------------
__global__ void k_sortscan(){
  int b = blockIdx.x;
  int t = threadIdx.x;        // 1024
  int lane = t & 31, wid = t >> 5;
  __shared__ float  s[2048];
  __shared__ double wsum[32];
  __shared__ double s_tot;
  for (int i = t; i < 2048; i += 1024) s[i] = (i < NN) ? g_right[b*NN+i] : 3.0e38f;
  __syncthreads();

  // bitonic ascending sort: smem steps for j>=64, register/shfl tail for j<=32
  for (int ksz = 2; ksz <= 2048; ksz <<= 1){
    for (int j = ksz >> 1; j >= 64; j >>= 1){
      for (int idx = t; idx < 2048; idx += 1024){
        int p = idx ^ j;
        if (p > idx){
          float a0 = s[idx], a1 = s[p];
          bool up = ((idx & ksz) == 0);
          if ((a0 > a1) == up){ s[idx] = a1; s[p] = a0; }
        }
      }
      __syncthreads();
    }
    // tail: thread t holds elements 2t, 2t+1
    float e0 = s[2*t], e1 = s[2*t+1];
    bool up = (((2*t) & ksz) == 0);
    int j0 = (ksz >> 1) < 32 ? (ksz >> 1) : 32;
    for (int j = j0; j >= 2; j >>= 1){
      int half = j >> 1;
      float o0 = __shfl_xor_sync(0xFFFFFFFFu, e0, half);
      float o1 = __shfl_xor_sync(0xFFFFFFFFu, e1, half);
      bool lower = ((t & half) == 0);
      bool keepmin = (lower == up);
      e0 = keepmin ? fminf(e0, o0) : fmaxf(e0, o0);
      e1 = keepmin ? fminf(e1, o1) : fmaxf(e1, o1);
    }
    { // j == 1 (within thread)
      float mn = fminf(e0, e1), mx = fmaxf(e0, e1);
      e0 = up ? mn : mx; e1 = up ? mx : mn;
    }
    s[2*t] = e0; s[2*t+1] = e1;
    __syncthreads();
  }
  for (int i = t; i < NN; i += 1024) g_Rs[b*2048+i] = s[i];

  // ---- pass 1: suffix sums of exp(Rs) via 2-level warp scan (double) ----
  {
    float v0 = (2*t   < NN) ? expf(s[2*t])   : 0.f;
    float v1 = (2*t+1 < NN) ? expf(s[2*t+1]) : 0.f;
    double lsum = (double)v0 + (double)v1;
    double val = lsum;
    #pragma unroll
    for (int off = 1; off < 32; off <<= 1){
      double nv = __shfl_up_sync(0xFFFFFFFFu, val, off);
      if (lane >= off) val += nv;
    }
    if (lane == 31) wsum[wid] = val;
    __syncthreads();
    if (wid == 0){
      double wv = wsum[lane];
      double wvs = wv;
      #pragma unroll
      for (int off = 1; off < 32; off <<= 1){
        double nv = __shfl_up_sync(0xFFFFFFFFu, wvs, off);
        if (lane >= off) wvs += nv;
      }
      wsum[lane] = wvs - wv;            // exclusive warp offset
      if (lane == 31) s_tot = wvs;
    }
    __syncthreads();
    double excl = wsum[wid] + val - lsum;
    double tot  = s_tot;
    g_suf[b*2048 + 2*t]   = (float)(tot - excl);
    g_suf[b*2048 + 2*t+1] = (float)(tot - (excl + (double)v0));
    __syncthreads();   // wsum reused below
  }
  // ---- pass 2: prefix sums of exp(0.2*Rs) ----
  {
    float v0 = (2*t   < NN) ? expf(0.2f*s[2*t])   : 0.f;
    float v1 = (2*t+1 < NN) ? expf(0.2f*s[2*t+1]) : 0.f;
    double lsum = (double)v0 + (double)v1;
    double val = lsum;
    #pragma unroll
    for (int off = 1; off < 32; off <<= 1){
      double nv = __shfl_up_sync(0xFFFFFFFFu, val, off);
      if (lane >= off) val += nv;
    }
    if (lane == 31) wsum[wid] = val;
    __syncthreads();
    if (wid == 0){
      double wv = wsum[lane];
      double wvs = wv;
      #pragma unroll
      for (int off = 1; off < 32; off <<= 1){
        double nv = __shfl_up_sync(0xFFFFFFFFu, wvs, off);
        if (lane >= off) wvs += nv;
      }
      wsum[lane] = wvs - wv;
    }
    __syncthreads();
    double excl = wsum[wid] + val - lsum;
    g_pre[b*2048 + 2*t]   = (float)excl;
    g_pre[b*2048 + 2*t+1] = (float)(excl + (double)v0);
  }
}

// ---------------- 3) edge weights: packed (attention+adj1, idx) at top-K ----------------
__global__ void k_weights(){
  int g = blockIdx.x*256 + threadIdx.x;
  if (g >= BB*NN) return;
  int b = g / NN;
  int m = g - b*NN;
  float L = g_left[g];
  float negL = -L;
  const float* Rs = g_Rs + b*2048;
  int lo = 0, hi = NN;
  while (lo < hi){ int mid = (lo+hi) >> 1; if (Rs[mid] < negL) lo = mid+1; else hi = mid; }
  float denom = expf(L)*g_suf[b*2048+lo] + expf(0.2f*L)*g_pre[b*2048+lo];
  float inv = 1.f/denom;
  float* wo = g_wi + (size_t)g*KK*2;
  #pragma unroll
  for (int k = 0; k < KK; k++){
    int n = g_idx[m*KK+k];
    float R = g_right[b*NN+n];
    float z = L + R;
    float e = (z >= 0.f) ? z : NSLOPE*z;
    wo[2*k]   = expf(e)*inv + g_adjw[m*KK+k];
    wo[2*k+1] = __int_as_float(n);
  }
}

// ---------------- 4) fused 2-iteration propagation, per (b, d-chunk) ----------------
__global__ __launch_bounds__(1024, 1) void k_propf(const float* __restrict__ x){
  extern __shared__ float sm[];
  float* sx = sm;          // x slice
  float* sh = sm + SLICE;  // h1 slice
  int b  = blockIdx.y;
  int d0 = blockIdx.x * DC;
  int tid = threadIdx.x;
  #pragma unroll
  for (int dl = 0; dl < DC; dl++){
    const float* xr = x + ((size_t)b*DD + d0 + dl)*NN;
    for (int n = tid; n < NN; n += 1024) sx[ROFF(n) + dl] = __ldg(xr + n);
  }
  __syncthreads();

  int mlane = tid >> 1;        // 512 m-lanes
  int h4    = (tid & 1) * 4;   // which float4 half of the 8-float chunk

  // iter 1: h1 = a*x + (1-a) * sum_k w_k x[idx_k]   (into sh)
  #pragma unroll
  for (int j = 0; j < 4; j++){
    int m = j*512 + mlane;
    if (m < NN){
      const float4* wi = reinterpret_cast<const float4*>(g_wi + ((size_t)(b*NN+m))*(KK*2));
      float ax=0.f, ay=0.f, az=0.f, aw=0.f;
      #pragma unroll
      for (int kk = 0; kk < KK/2; kk++){
        float4 p = __ldg(wi + kk);
        const float4 v1 = *reinterpret_cast<const float4*>(sx + ROFF(__float_as_int(p.y)) + h4);
        ax += p.x*v1.x; ay += p.x*v1.y; az += p.x*v1.z; aw += p.x*v1.w;
        const float4 v2 = *reinterpret_cast<const float4*>(sx + ROFF(__float_as_int(p.w)) + h4);
        ax += p.z*v2.x; ay += p.z*v2.y; az += p.z*v2.z; aw += p.z*v2.w;
      }
      int rm = ROFF(m) + h4;
      float4 xm = *reinterpret_cast<const float4*>(sx + rm);
      float4 r;
      r.x = ALPHA*xm.x + OMA*ax;
      r.y = ALPHA*xm.y + OMA*ay;
      r.z = ALPHA*xm.z + OMA*az;
      r.w = ALPHA*xm.w + OMA*aw;
      *reinterpret_cast<float4*>(sh + rm) = r;
    }
  }
  __syncthreads();

  // iter 2: h2 = a*x + (1-a) * sum_k w_k h1[idx_k]   (to global, [b][d][n])
  #pragma unroll
  for (int j = 0; j < 4; j++){
    int m = j*512 + mlane;
    if (m < NN){
      const float4* wi = reinterpret_cast<const float4*>(g_wi + ((size_t)(b*NN+m))*(KK*2));
      float ax=0.f, ay=0.f, az=0.f, aw=0.f;
      #pragma unroll
      for (int kk = 0; kk < KK/2; kk++){
        float4 p = __ldg(wi + kk);
        const float4 v1 = *reinterpret_cast<const float4*>(sh + ROFF(__float_as_int(p.y)) + h4);
        ax += p.x*v1.x; ay += p.x*v1.y; az += p.x*v1.z; aw += p.x*v1.w;
        const float4 v2 = *reinterpret_cast<const float4*>(sh + ROFF(__float_as_int(p.w)) + h4);
        ax += p.z*v2.x; ay += p.z*v2.y; az += p.z*v2.z; aw += p.z*v2.w;
      }
      float4 xm = *reinterpret_cast<const float4*>(sx + ROFF(m) + h4);
      float r0 = ALPHA*xm.x + OMA*ax;
      float r1 = ALPHA*xm.y + OMA*ay;
      float r2 = ALPHA*xm.z + OMA*az;
      float r3 = ALPHA*xm.w + OMA*aw;
      size_t o = ((size_t)b*DD + d0 + h4)*NN + m;
      g_h2[o]        = r0;
      g_h2[o + NN]   = r1;
      g_h2[o + 2*NN] = r2;
      g_h2[o + 3*NN] = r3;
    }
  }
}

// ---------------- 5) output: ho[b,o,t,n] = W1 @ h2 + b1 (h2 in [b][d][n]) ----------------
__global__ void k_out(const float* __restrict__ W1, const float* __restrict__ b1,
                      float* __restrict__ out){
  __shared__ __align__(16) float w1s[32*36];
  __shared__ float b1s[32];
  int b = blockIdx.z;
  int t = blockIdx.y;
  int n = blockIdx.x*256 + threadIdx.x;
  for (int i = threadIdx.x; i < 1024; i += 256){ int o = i >> 5, c = i & 31; w1s[o*36 + c] = W1[i]; }
  if (threadIdx.x < 32) b1s[threadIdx.x] = b1[threadIdx.x];
  __syncthreads();
  if (n >= NN) return;
  float xv[CC];
  const float* hp = g_h2 + ((size_t)b*DD + t)*NN + n;
  #pragma unroll
  for (int c = 0; c < CC; c++) xv[c] = __ldg(hp + (size_t)c*TT*NN);
  size_t ob = ((size_t)b*CC*TT + t)*NN + n;
  #pragma unroll
  for (int o = 0; o < CC; o++){
    float acc = b1s[o];
    const float4* wr = reinterpret_cast<const float4*>(w1s + o*36);
    #pragma unroll
    for (int c4 = 0; c4 < CC/4; c4++){
      float4 w = wr[c4];
      acc += w.x*xv[4*c4] + w.y*xv[4*c4+1] + w.z*xv[4*c4+2] + w.w*xv[4*c4+3];
    }
    out[ob + (size_t)o*TT*NN] = acc;
  }
}

// ---------------- launch ----------------
extern "C" void kernel_launch(void* const* d_in, const int* in_sizes, int n_in,
                              void* d_out, int out_size){
  const float* x   = (const float*)d_in[0];
  const float* adj = (const float*)d_in[1];
  const float* W1  = (const float*)d_in[2];
  const float* b1  = (const float*)d_in[3];
  const float* W2  = (const float*)d_in[4];
  const float* b2  = (const float*)d_in[5];
  const float* a   = (const float*)d_in[6];
  float* out = (float*)d_out;

  cudaFuncSetAttribute(k_propf, cudaFuncAttributeMaxDynamicSharedMemorySize, PROP_SMEM);

  k_front<<<NN + 128, 256>>>(adj, x, W2, b2, a);      // #1
  k_sortscan<<<BB, 1024>>>();                         // #2
  k_weights<<<(BB*NN+255)/256, 256>>>();              // #3
  k_propf<<<dim3(NCH, BB), 1024, PROP_SMEM>>>(x);     // #4  <- ncu capture lands here
  k_out<<<dim3((NN+255)/256, TT, BB), 256>>>(W1, b1, out); // #5
}